// round 10
// baseline (speedup 1.0000x reference)
#include <cuda_runtime.h>
#include <cstdint>

#define DIM   64
#define NPAD  53248          // 1024 * 52 (>= N, padded for single-block scan)
#define EMAX  800000

// Scratch (allocation-free rule: __device__ globals).
// g_deg is zero on first call (static init) and re-zeroed by k_gather every
// launch after consumption -> invariant holds across graph replays.
__device__ int   g_deg[NPAD];
__device__ int   g_start[NPAD];   // scan writes start; scatter bumps it to start+deg
__device__ int   g_cols[EMAX];
__device__ float g_agg[(size_t)NPAD * DIM];   // normalized row sums

// ---------------------------------------------------------------------------
// 1. histogram of destination rows (4 edges per thread, int4 reads)
// ---------------------------------------------------------------------------
__global__ __launch_bounds__(256) void k_hist(const int* __restrict__ ei, int E) {
    int i = (blockIdx.x * blockDim.x + threadIdx.x) * 4;
    if (i + 3 < E) {
        int4 r = *(const int4*)(ei + i);
        atomicAdd(&g_deg[r.x], 1);
        atomicAdd(&g_deg[r.y], 1);
        atomicAdd(&g_deg[r.z], 1);
        atomicAdd(&g_deg[r.w], 1);
    } else {
        for (int k = i; k < E; k++) atomicAdd(&g_deg[ei[k]], 1);
    }
}

// ---------------------------------------------------------------------------
// 2. single-block exclusive scan over all NPAD degrees -> g_start.
// ---------------------------------------------------------------------------
__global__ __launch_bounds__(1024) void k_scan() {
    __shared__ int s[1024];
    int tid = threadIdx.x;
    const int4* dv = (const int4*)g_deg + tid * 13;

    int tot = 0;
    int4 loc[13];
    #pragma unroll
    for (int i = 0; i < 13; i++) {
        loc[i] = dv[i];
        tot += loc[i].x + loc[i].y + loc[i].z + loc[i].w;
    }
    s[tid] = tot;
    __syncthreads();
    #pragma unroll
    for (int off = 1; off < 1024; off <<= 1) {
        int t = (tid >= off) ? s[tid - off] : 0;
        __syncthreads();
        s[tid] += t;
        __syncthreads();
    }
    int run = s[tid] - tot;     // exclusive prefix of this thread's chunk

    int4* sv = (int4*)g_start + tid * 13;
    #pragma unroll
    for (int i = 0; i < 13; i++) {
        int4 v = loc[i];
        int4 o;
        o.x = run; run += v.x;
        o.y = run; run += v.y;
        o.z = run; run += v.z;
        o.w = run; run += v.w;
        sv[i] = o;
    }
}

// ---------------------------------------------------------------------------
// 3. scatter source cols into CSR order; cursor IS g_start (ends at start+deg).
// ---------------------------------------------------------------------------
__global__ __launch_bounds__(256) void k_scatter(const int* __restrict__ ei, int E) {
    int i = (blockIdx.x * blockDim.x + threadIdx.x) * 4;
    if (i + 3 < E) {
        int4 r = *(const int4*)(ei + i);
        int4 c = *(const int4*)(ei + E + i);
        g_cols[atomicAdd(&g_start[r.x], 1)] = c.x;
        g_cols[atomicAdd(&g_start[r.y], 1)] = c.y;
        g_cols[atomicAdd(&g_start[r.z], 1)] = c.z;
        g_cols[atomicAdd(&g_start[r.w], 1)] = c.w;
    } else {
        for (int k = i; k < E; k++)
            g_cols[atomicAdd(&g_start[ei[k]], 1)] = ei[E + k];
    }
}

// ---------------------------------------------------------------------------
// 4. gather-sum: 8 threads per row, 2 float4 chunks per thread, 4-edge quads
//    with pipelined col prefetch. Base = g_start[row] - deg (post-scatter).
//    Normalization + deg reset folded in. No smem.
// ---------------------------------------------------------------------------
__global__ __launch_bounds__(256) void k_gather(const float* __restrict__ x, int n) {
    int row = blockIdx.x * 32 + (threadIdx.x >> 3);
    int t   = threadIdx.x & 7;          // chunk pair: float4s at t*8 and t*8+4
    if (row >= n) return;

    int c = g_deg[row];
    int s = g_start[row] - c;           // scatter advanced start by deg
    if (t == 0) g_deg[row] = 0;         // reset for next replay (c already read)

    const float* __restrict__ xb = x + t * 8;

    float4 a0 = make_float4(0.f, 0.f, 0.f, 0.f);
    float4 a1 = make_float4(0.f, 0.f, 0.f, 0.f);

    int nq = c >> 2;
    if (nq > 0) {
        int c0 = g_cols[s + 0];
        int c1 = g_cols[s + 1];
        int c2 = g_cols[s + 2];
        int c3 = g_cols[s + 3];
        for (int q = 1; q < nq; q++) {
            const float* p0 = xb + (size_t)c0 * DIM;
            const float* p1 = xb + (size_t)c1 * DIM;
            const float* p2 = xb + (size_t)c2 * DIM;
            const float* p3 = xb + (size_t)c3 * DIM;
            float4 v00 = *(const float4*)(p0);
            float4 v01 = *(const float4*)(p0 + 4);
            float4 v10 = *(const float4*)(p1);
            float4 v11 = *(const float4*)(p1 + 4);
            float4 v20 = *(const float4*)(p2);
            float4 v21 = *(const float4*)(p2 + 4);
            float4 v30 = *(const float4*)(p3);
            float4 v31 = *(const float4*)(p3 + 4);
            int nb = s + q * 4;                 // prefetch next quad of cols
            c0 = g_cols[nb + 0];
            c1 = g_cols[nb + 1];
            c2 = g_cols[nb + 2];
            c3 = g_cols[nb + 3];
            a0.x += v00.x + v10.x + v20.x + v30.x;
            a0.y += v00.y + v10.y + v20.y + v30.y;
            a0.z += v00.z + v10.z + v20.z + v30.z;
            a0.w += v00.w + v10.w + v20.w + v30.w;
            a1.x += v01.x + v11.x + v21.x + v31.x;
            a1.y += v01.y + v11.y + v21.y + v31.y;
            a1.z += v01.z + v11.z + v21.z + v31.z;
            a1.w += v01.w + v11.w + v21.w + v31.w;
        }
        {   // drain last quad
            const float* p0 = xb + (size_t)c0 * DIM;
            const float* p1 = xb + (size_t)c1 * DIM;
            const float* p2 = xb + (size_t)c2 * DIM;
            const float* p3 = xb + (size_t)c3 * DIM;
            float4 v00 = *(const float4*)(p0);
            float4 v01 = *(const float4*)(p0 + 4);
            float4 v10 = *(const float4*)(p1);
            float4 v11 = *(const float4*)(p1 + 4);
            float4 v20 = *(const float4*)(p2);
            float4 v21 = *(const float4*)(p2 + 4);
            float4 v30 = *(const float4*)(p3);
            float4 v31 = *(const float4*)(p3 + 4);
            a0.x += v00.x + v10.x + v20.x + v30.x;
            a0.y += v00.y + v10.y + v20.y + v30.y;
            a0.z += v00.z + v10.z + v20.z + v30.z;
            a0.w += v00.w + v10.w + v20.w + v30.w;
            a1.x += v01.x + v11.x + v21.x + v31.x;
            a1.y += v01.y + v11.y + v21.y + v31.y;
            a1.z += v01.z + v11.z + v21.z + v31.z;
            a1.w += v01.w + v11.w + v21.w + v31.w;
        }
    }
    for (int j = nq << 2; j < c; j++) {
        int cc = g_cols[s + j];
        const float* p = xb + (size_t)cc * DIM;
        float4 v0 = *(const float4*)(p);
        float4 v1 = *(const float4*)(p + 4);
        a0.x += v0.x; a0.y += v0.y; a0.z += v0.z; a0.w += v0.w;
        a1.x += v1.x; a1.y += v1.y; a1.z += v1.z; a1.w += v1.w;
    }

    float inv = 1.0f / ((float)c + 1e-6f);
    a0.x *= inv; a0.y *= inv; a0.z *= inv; a0.w *= inv;
    a1.x *= inv; a1.y *= inv; a1.z *= inv; a1.w *= inv;

    float4* dst = (float4*)(g_agg + (size_t)row * DIM + t * 8);
    dst[0] = a0;
    dst[1] = a1;
}

// ---------------------------------------------------------------------------
// 5. out = agg @ W^T + b   (agg already normalized)
// ---------------------------------------------------------------------------
__global__ __launch_bounds__(256) void out_kernel(
    const float* __restrict__ W,
    const float* __restrict__ b,
    float* __restrict__ out,
    int n)
{
    __shared__ float sW[64 * 68];
    __shared__ float sA[64 * 68];
    __shared__ float sB[64];

    const int tid  = threadIdx.x;
    const int base = blockIdx.x * 64;

    for (int idx = tid; idx < 64 * 64; idx += 256) {
        int j = idx >> 6;
        int k = idx & 63;
        sW[k * 68 + j] = W[idx];
    }
    if (tid < 64) sB[tid] = b[tid];

    #pragma unroll
    for (int p = 0; p < 4; p++) {
        int idx  = tid + p * 256;
        int nd   = idx >> 4;
        int ch   = idx & 15;
        int node = base + nd;
        float4 v = make_float4(0.f, 0.f, 0.f, 0.f);
        if (node < n)
            v = *(const float4*)&g_agg[(size_t)node * DIM + ch * 4];
        *(float4*)&sA[nd * 68 + ch * 4] = v;
    }
    __syncthreads();

    const int tx = tid & 15;
    const int ty = tid >> 4;

    float acc[4][4];
    #pragma unroll
    for (int i = 0; i < 4; i++)
        #pragma unroll
        for (int c = 0; c < 4; c++)
            acc[i][c] = 0.f;

    #pragma unroll
    for (int k = 0; k < 64; k += 4) {
        float4 wv0 = *(const float4*)&sW[(k + 0) * 68 + tx * 4];
        float4 wv1 = *(const float4*)&sW[(k + 1) * 68 + tx * 4];
        float4 wv2 = *(const float4*)&sW[(k + 2) * 68 + tx * 4];
        float4 wv3 = *(const float4*)&sW[(k + 3) * 68 + tx * 4];
        #pragma unroll
        for (int i = 0; i < 4; i++) {
            float4 av = *(const float4*)&sA[(ty * 4 + i) * 68 + k];
            acc[i][0] += av.x * wv0.x + av.y * wv1.x + av.z * wv2.x + av.w * wv3.x;
            acc[i][1] += av.x * wv0.y + av.y * wv1.y + av.z * wv2.y + av.w * wv3.y;
            acc[i][2] += av.x * wv0.z + av.y * wv1.z + av.z * wv2.z + av.w * wv3.z;
            acc[i][3] += av.x * wv0.w + av.y * wv1.w + av.z * wv2.w + av.w * wv3.w;
        }
    }

    #pragma unroll
    for (int i = 0; i < 4; i++) {
        int node = base + ty * 4 + i;
        if (node < n) {
            float4 o;
            o.x = acc[i][0] + sB[tx * 4 + 0];
            o.y = acc[i][1] + sB[tx * 4 + 1];
            o.z = acc[i][2] + sB[tx * 4 + 2];
            o.w = acc[i][3] + sB[tx * 4 + 3];
            *(float4*)&out[(size_t)node * DIM + tx * 4] = o;
        }
    }
}

// ---------------------------------------------------------------------------
// kernel_launch — inputs: x [N*64 f32], edge_index [2*E i32], W [64*64 f32],
// b [64 f32]; output [N*64 f32].
// ---------------------------------------------------------------------------
extern "C" void kernel_launch(void* const* d_in, const int* in_sizes, int n_in,
                              void* d_out, int out_size) {
    const float* x  = (const float*)d_in[0];
    const int*   ei = (const int*)d_in[1];
    const float* W  = (const float*)d_in[2];
    const float* b  = (const float*)d_in[3];
    float*       out = (float*)d_out;

    int n = in_sizes[0] / DIM;       // 50000
    int E = in_sizes[1] / 2;         // 800000

    int eblocks = (E / 4 + 255) / 256 + 1;

    k_hist<<<eblocks, 256>>>(ei, E);
    k_scan<<<1, 1024>>>();
    k_scatter<<<eblocks, 256>>>(ei, E);
    k_gather<<<(n + 31) / 32, 256>>>(x, n);
    out_kernel<<<(n + 63) / 64, 256>>>(W, b, out, n);
}

// round 11
// speedup vs baseline: 1.3736x; 1.3736x over previous
#include <cuda_runtime.h>
#include <cstdint>

#define DIM   64
#define NPAD  53248          // 1024 * 52 (>= N, padded for single-block scan)
#define EMAX  800000

// Scratch (allocation-free rule: __device__ globals).
// g_deg is zero on first call (static init) and re-zeroed by k_gather every
// launch after consumption -> invariant holds across graph replays.
__device__ int   g_deg[NPAD];
__device__ int   g_start[NPAD];   // scan writes start; scatter bumps it to start+deg
__device__ int   g_cols[EMAX];
__device__ float g_agg[(size_t)NPAD * DIM];   // normalized row sums

// ---------------------------------------------------------------------------
// 1. histogram of destination rows (4 edges per thread, int4 reads)
// ---------------------------------------------------------------------------
__global__ __launch_bounds__(256) void k_hist(const int* __restrict__ ei, int E) {
    int i = (blockIdx.x * blockDim.x + threadIdx.x) * 4;
    if (i + 3 < E) {
        int4 r = *(const int4*)(ei + i);
        atomicAdd(&g_deg[r.x], 1);
        atomicAdd(&g_deg[r.y], 1);
        atomicAdd(&g_deg[r.z], 1);
        atomicAdd(&g_deg[r.w], 1);
    } else {
        for (int k = i; k < E; k++) atomicAdd(&g_deg[ei[k]], 1);
    }
}

// ---------------------------------------------------------------------------
// 2. single-block exclusive scan over all NPAD degrees -> g_start.
// ---------------------------------------------------------------------------
__global__ __launch_bounds__(1024) void k_scan() {
    __shared__ int s[1024];
    int tid = threadIdx.x;
    const int4* dv = (const int4*)g_deg + tid * 13;

    int tot = 0;
    int4 loc[13];
    #pragma unroll
    for (int i = 0; i < 13; i++) {
        loc[i] = dv[i];
        tot += loc[i].x + loc[i].y + loc[i].z + loc[i].w;
    }
    s[tid] = tot;
    __syncthreads();
    #pragma unroll
    for (int off = 1; off < 1024; off <<= 1) {
        int t = (tid >= off) ? s[tid - off] : 0;
        __syncthreads();
        s[tid] += t;
        __syncthreads();
    }
    int run = s[tid] - tot;     // exclusive prefix of this thread's chunk

    int4* sv = (int4*)g_start + tid * 13;
    #pragma unroll
    for (int i = 0; i < 13; i++) {
        int4 v = loc[i];
        int4 o;
        o.x = run; run += v.x;
        o.y = run; run += v.y;
        o.z = run; run += v.z;
        o.w = run; run += v.w;
        sv[i] = o;
    }
}

// ---------------------------------------------------------------------------
// 3. scatter source cols into CSR order; cursor IS g_start (ends at start+deg).
// ---------------------------------------------------------------------------
__global__ __launch_bounds__(256) void k_scatter(const int* __restrict__ ei, int E) {
    int i = (blockIdx.x * blockDim.x + threadIdx.x) * 4;
    if (i + 3 < E) {
        int4 r = *(const int4*)(ei + i);
        int4 c = *(const int4*)(ei + E + i);
        g_cols[atomicAdd(&g_start[r.x], 1)] = c.x;
        g_cols[atomicAdd(&g_start[r.y], 1)] = c.y;
        g_cols[atomicAdd(&g_start[r.z], 1)] = c.z;
        g_cols[atomicAdd(&g_start[r.w], 1)] = c.w;
    } else {
        for (int k = i; k < E; k++)
            g_cols[atomicAdd(&g_start[ei[k]], 1)] = ei[E + k];
    }
}

// ---------------------------------------------------------------------------
// 4. gather-sum: 16 threads per row, one float4 chunk per thread, 4-edge quads
//    with pipelined col prefetch. __launch_bounds__(256, 8) caps regs at 32 ->
//    up to 2048 threads/SM resident for latency hiding (this is the change).
//    Base = g_start[row] - deg (post-scatter). Normalize + deg reset folded in.
// ---------------------------------------------------------------------------
__global__ __launch_bounds__(256, 8) void k_gather(const float* __restrict__ x, int n) {
    int row = blockIdx.x * 16 + (threadIdx.x >> 4);
    int t   = threadIdx.x & 15;
    if (row >= n) return;

    int c = g_deg[row];
    int s = g_start[row] - c;           // scatter advanced start by deg
    if (t == 0) g_deg[row] = 0;         // reset for next replay (c already read)

    const float* __restrict__ xb = x + t * 4;

    float4 acc = make_float4(0.f, 0.f, 0.f, 0.f);

    int nq = c >> 2;
    if (nq > 0) {
        int c0 = g_cols[s + 0];
        int c1 = g_cols[s + 1];
        int c2 = g_cols[s + 2];
        int c3 = g_cols[s + 3];
        for (int q = 1; q < nq; q++) {
            float4 v0 = *(const float4*)(xb + (size_t)c0 * DIM);
            float4 v1 = *(const float4*)(xb + (size_t)c1 * DIM);
            float4 v2 = *(const float4*)(xb + (size_t)c2 * DIM);
            float4 v3 = *(const float4*)(xb + (size_t)c3 * DIM);
            int nb = s + q * 4;                 // prefetch next quad of cols
            c0 = g_cols[nb + 0];
            c1 = g_cols[nb + 1];
            c2 = g_cols[nb + 2];
            c3 = g_cols[nb + 3];
            acc.x += v0.x + v1.x + v2.x + v3.x;
            acc.y += v0.y + v1.y + v2.y + v3.y;
            acc.z += v0.z + v1.z + v2.z + v3.z;
            acc.w += v0.w + v1.w + v2.w + v3.w;
        }
        {   // drain last quad
            float4 v0 = *(const float4*)(xb + (size_t)c0 * DIM);
            float4 v1 = *(const float4*)(xb + (size_t)c1 * DIM);
            float4 v2 = *(const float4*)(xb + (size_t)c2 * DIM);
            float4 v3 = *(const float4*)(xb + (size_t)c3 * DIM);
            acc.x += v0.x + v1.x + v2.x + v3.x;
            acc.y += v0.y + v1.y + v2.y + v3.y;
            acc.z += v0.z + v1.z + v2.z + v3.z;
            acc.w += v0.w + v1.w + v2.w + v3.w;
        }
    }
    for (int j = nq << 2; j < c; j++) {
        int cc = g_cols[s + j];
        float4 v = *(const float4*)(xb + (size_t)cc * DIM);
        acc.x += v.x; acc.y += v.y; acc.z += v.z; acc.w += v.w;
    }

    float inv = 1.0f / ((float)c + 1e-6f);
    acc.x *= inv; acc.y *= inv; acc.z *= inv; acc.w *= inv;
    *(float4*)&g_agg[(size_t)row * DIM + t * 4] = acc;
}

// ---------------------------------------------------------------------------
// 5. out = agg @ W^T + b   (agg already normalized)
// ---------------------------------------------------------------------------
__global__ __launch_bounds__(256) void out_kernel(
    const float* __restrict__ W,
    const float* __restrict__ b,
    float* __restrict__ out,
    int n)
{
    __shared__ float sW[64 * 68];
    __shared__ float sA[64 * 68];
    __shared__ float sB[64];

    const int tid  = threadIdx.x;
    const int base = blockIdx.x * 64;

    for (int idx = tid; idx < 64 * 64; idx += 256) {
        int j = idx >> 6;
        int k = idx & 63;
        sW[k * 68 + j] = W[idx];
    }
    if (tid < 64) sB[tid] = b[tid];

    #pragma unroll
    for (int p = 0; p < 4; p++) {
        int idx  = tid + p * 256;
        int nd   = idx >> 4;
        int ch   = idx & 15;
        int node = base + nd;
        float4 v = make_float4(0.f, 0.f, 0.f, 0.f);
        if (node < n)
            v = *(const float4*)&g_agg[(size_t)node * DIM + ch * 4];
        *(float4*)&sA[nd * 68 + ch * 4] = v;
    }
    __syncthreads();

    const int tx = tid & 15;
    const int ty = tid >> 4;

    float acc[4][4];
    #pragma unroll
    for (int i = 0; i < 4; i++)
        #pragma unroll
        for (int c = 0; c < 4; c++)
            acc[i][c] = 0.f;

    #pragma unroll
    for (int k = 0; k < 64; k += 4) {
        float4 wv0 = *(const float4*)&sW[(k + 0) * 68 + tx * 4];
        float4 wv1 = *(const float4*)&sW[(k + 1) * 68 + tx * 4];
        float4 wv2 = *(const float4*)&sW[(k + 2) * 68 + tx * 4];
        float4 wv3 = *(const float4*)&sW[(k + 3) * 68 + tx * 4];
        #pragma unroll
        for (int i = 0; i < 4; i++) {
            float4 av = *(const float4*)&sA[(ty * 4 + i) * 68 + k];
            acc[i][0] += av.x * wv0.x + av.y * wv1.x + av.z * wv2.x + av.w * wv3.x;
            acc[i][1] += av.x * wv0.y + av.y * wv1.y + av.z * wv2.y + av.w * wv3.y;
            acc[i][2] += av.x * wv0.z + av.y * wv1.z + av.z * wv2.z + av.w * wv3.z;
            acc[i][3] += av.x * wv0.w + av.y * wv1.w + av.z * wv2.w + av.w * wv3.w;
        }
    }

    #pragma unroll
    for (int i = 0; i < 4; i++) {
        int node = base + ty * 4 + i;
        if (node < n) {
            float4 o;
            o.x = acc[i][0] + sB[tx * 4 + 0];
            o.y = acc[i][1] + sB[tx * 4 + 1];
            o.z = acc[i][2] + sB[tx * 4 + 2];
            o.w = acc[i][3] + sB[tx * 4 + 3];
            *(float4*)&out[(size_t)node * DIM + tx * 4] = o;
        }
    }
}

// ---------------------------------------------------------------------------
// kernel_launch — inputs: x [N*64 f32], edge_index [2*E i32], W [64*64 f32],
// b [64 f32]; output [N*64 f32].
// ---------------------------------------------------------------------------
extern "C" void kernel_launch(void* const* d_in, const int* in_sizes, int n_in,
                              void* d_out, int out_size) {
    const float* x  = (const float*)d_in[0];
    const int*   ei = (const int*)d_in[1];
    const float* W  = (const float*)d_in[2];
    const float* b  = (const float*)d_in[3];
    float*       out = (float*)d_out;

    int n = in_sizes[0] / DIM;       // 50000
    int E = in_sizes[1] / 2;         // 800000

    int eblocks = (E / 4 + 255) / 256 + 1;

    k_hist<<<eblocks, 256>>>(ei, E);
    k_scan<<<1, 1024>>>();
    k_scatter<<<eblocks, 256>>>(ei, E);
    k_gather<<<(n + 15) / 16, 256>>>(x, n);
    out_kernel<<<(n + 63) / 64, 256>>>(W, b, out, n);
}

// round 13
// speedup vs baseline: 1.4920x; 1.0862x over previous
#include <cuda_runtime.h>
#include <cuda_fp16.h>
#include <cstdint>

#define DIM   64
#define NPAD  53248          // 1024 * 52 (>= N, padded for single-block scan)
#define EMAX  800000

// Scratch (allocation-free rule: __device__ globals).
// g_deg is zero on first call (static init) and re-zeroed by k_gather every
// launch after consumption -> invariant holds across graph replays.
__device__ int    g_deg[NPAD];
__device__ int    g_start[NPAD];   // scan writes start; scatter bumps it to start+deg
__device__ int    g_cols[EMAX];
__device__ __half g_xh[(size_t)NPAD * DIM];   // fp16 mirror of x
__device__ float  g_agg[(size_t)NPAD * DIM];  // normalized row sums (fp32)

// ---------------------------------------------------------------------------
// 0. convert x (fp32) -> g_xh (fp16). One thread per 8 elements.
// ---------------------------------------------------------------------------
__global__ __launch_bounds__(256) void k_cvt(const float* __restrict__ x, int n) {
    int i = blockIdx.x * 256 + threadIdx.x;
    int total = n * (DIM / 8);
    if (i >= total) return;
    const float4* src = (const float4*)x + (size_t)i * 2;
    float4 a = src[0];
    float4 bq = src[1];
    __half2 h0 = __floats2half2_rn(a.x,  a.y);
    __half2 h1 = __floats2half2_rn(a.z,  a.w);
    __half2 h2 = __floats2half2_rn(bq.x, bq.y);
    __half2 h3 = __floats2half2_rn(bq.z, bq.w);
    uint4 o;
    o.x = *(const unsigned*)&h0;
    o.y = *(const unsigned*)&h1;
    o.z = *(const unsigned*)&h2;
    o.w = *(const unsigned*)&h3;
    ((uint4*)g_xh)[i] = o;
}

// ---------------------------------------------------------------------------
// 1. histogram of destination rows (4 edges per thread, int4 reads)
// ---------------------------------------------------------------------------
__global__ __launch_bounds__(256) void k_hist(const int* __restrict__ ei, int E) {
    int i = (blockIdx.x * blockDim.x + threadIdx.x) * 4;
    if (i + 3 < E) {
        int4 r = *(const int4*)(ei + i);
        atomicAdd(&g_deg[r.x], 1);
        atomicAdd(&g_deg[r.y], 1);
        atomicAdd(&g_deg[r.z], 1);
        atomicAdd(&g_deg[r.w], 1);
    } else {
        for (int k = i; k < E; k++) atomicAdd(&g_deg[ei[k]], 1);
    }
}

// ---------------------------------------------------------------------------
// 2. single-block exclusive scan over all NPAD degrees -> g_start.
// ---------------------------------------------------------------------------
__global__ __launch_bounds__(1024) void k_scan() {
    __shared__ int s[1024];
    int tid = threadIdx.x;
    const int4* dv = (const int4*)g_deg + tid * 13;

    int tot = 0;
    int4 loc[13];
    #pragma unroll
    for (int i = 0; i < 13; i++) {
        loc[i] = dv[i];
        tot += loc[i].x + loc[i].y + loc[i].z + loc[i].w;
    }
    s[tid] = tot;
    __syncthreads();
    #pragma unroll
    for (int off = 1; off < 1024; off <<= 1) {
        int t = (tid >= off) ? s[tid - off] : 0;
        __syncthreads();
        s[tid] += t;
        __syncthreads();
    }
    int run = s[tid] - tot;     // exclusive prefix of this thread's chunk

    int4* sv = (int4*)g_start + tid * 13;
    #pragma unroll
    for (int i = 0; i < 13; i++) {
        int4 v = loc[i];
        int4 o;
        o.x = run; run += v.x;
        o.y = run; run += v.y;
        o.z = run; run += v.z;
        o.w = run; run += v.w;
        sv[i] = o;
    }
}

// ---------------------------------------------------------------------------
// 3. scatter source cols into CSR order; cursor IS g_start (ends at start+deg).
// ---------------------------------------------------------------------------
__global__ __launch_bounds__(256) void k_scatter(const int* __restrict__ ei, int E) {
    int i = (blockIdx.x * blockDim.x + threadIdx.x) * 4;
    if (i + 3 < E) {
        int4 r = *(const int4*)(ei + i);
        int4 c = *(const int4*)(ei + E + i);
        g_cols[atomicAdd(&g_start[r.x], 1)] = c.x;
        g_cols[atomicAdd(&g_start[r.y], 1)] = c.y;
        g_cols[atomicAdd(&g_start[r.z], 1)] = c.z;
        g_cols[atomicAdd(&g_start[r.w], 1)] = c.w;
    } else {
        for (int k = i; k < E; k++)
            g_cols[atomicAdd(&g_start[ei[k]], 1)] = ei[E + k];
    }
}

// ---------------------------------------------------------------------------
// 4. gather-sum over fp16 x: 8 threads per row (row = 128B), one uint4 =
//    8 halfs per edge per thread, fp32 accumulation, 4-edge quads with
//    pipelined col prefetch. Base = g_start[row] - deg. Normalize + deg reset.
// ---------------------------------------------------------------------------
__global__ __launch_bounds__(256, 8) void k_gather(int n) {
    int row = blockIdx.x * 32 + (threadIdx.x >> 3);
    int t   = threadIdx.x & 7;
    if (row >= n) return;

    int c = g_deg[row];
    int s = g_start[row] - c;           // scatter advanced start by deg
    if (t == 0) g_deg[row] = 0;         // reset for next replay (c already read)

    const __half* __restrict__ xb = g_xh + t * 8;

    float2 a0 = make_float2(0.f, 0.f);
    float2 a1 = make_float2(0.f, 0.f);
    float2 a2 = make_float2(0.f, 0.f);
    float2 a3 = make_float2(0.f, 0.f);

    int nq = c >> 2;
    if (nq > 0) {
        int c0 = g_cols[s + 0];
        int c1 = g_cols[s + 1];
        int c2 = g_cols[s + 2];
        int c3 = g_cols[s + 3];
        for (int q = 1; q < nq; q++) {
            uint4 v0 = *(const uint4*)(xb + (size_t)c0 * DIM);
            uint4 v1 = *(const uint4*)(xb + (size_t)c1 * DIM);
            uint4 v2 = *(const uint4*)(xb + (size_t)c2 * DIM);
            uint4 v3 = *(const uint4*)(xb + (size_t)c3 * DIM);
            int nb = s + q * 4;                 // prefetch next quad of cols
            c0 = g_cols[nb + 0];
            c1 = g_cols[nb + 1];
            c2 = g_cols[nb + 2];
            c3 = g_cols[nb + 3];
            #pragma unroll
            for (int e = 0; e < 4; e++) {
                uint4 v = (e == 0) ? v0 : (e == 1) ? v1 : (e == 2) ? v2 : v3;
                float2 f0 = __half22float2(*(const __half2*)&v.x);
                float2 f1 = __half22float2(*(const __half2*)&v.y);
                float2 f2 = __half22float2(*(const __half2*)&v.z);
                float2 f3 = __half22float2(*(const __half2*)&v.w);
                a0.x += f0.x; a0.y += f0.y;
                a1.x += f1.x; a1.y += f1.y;
                a2.x += f2.x; a2.y += f2.y;
                a3.x += f3.x; a3.y += f3.y;
            }
        }
        {   // drain last quad
            uint4 v0 = *(const uint4*)(xb + (size_t)c0 * DIM);
            uint4 v1 = *(const uint4*)(xb + (size_t)c1 * DIM);
            uint4 v2 = *(const uint4*)(xb + (size_t)c2 * DIM);
            uint4 v3 = *(const uint4*)(xb + (size_t)c3 * DIM);
            #pragma unroll
            for (int e = 0; e < 4; e++) {
                uint4 v = (e == 0) ? v0 : (e == 1) ? v1 : (e == 2) ? v2 : v3;
                float2 f0 = __half22float2(*(const __half2*)&v.x);
                float2 f1 = __half22float2(*(const __half2*)&v.y);
                float2 f2 = __half22float2(*(const __half2*)&v.z);
                float2 f3 = __half22float2(*(const __half2*)&v.w);
                a0.x += f0.x; a0.y += f0.y;
                a1.x += f1.x; a1.y += f1.y;
                a2.x += f2.x; a2.y += f2.y;
                a3.x += f3.x; a3.y += f3.y;
            }
        }
    }
    for (int j = nq << 2; j < c; j++) {
        int cc = g_cols[s + j];
        uint4 v = *(const uint4*)(xb + (size_t)cc * DIM);
        float2 f0 = __half22float2(*(const __half2*)&v.x);
        float2 f1 = __half22float2(*(const __half2*)&v.y);
        float2 f2 = __half22float2(*(const __half2*)&v.z);
        float2 f3 = __half22float2(*(const __half2*)&v.w);
        a0.x += f0.x; a0.y += f0.y;
        a1.x += f1.x; a1.y += f1.y;
        a2.x += f2.x; a2.y += f2.y;
        a3.x += f3.x; a3.y += f3.y;
    }

    float inv = 1.0f / ((float)c + 1e-6f);
    float4 o0 = make_float4(a0.x * inv, a0.y * inv, a1.x * inv, a1.y * inv);
    float4 o1 = make_float4(a2.x * inv, a2.y * inv, a3.x * inv, a3.y * inv);
    float4* dst = (float4*)(g_agg + (size_t)row * DIM + t * 8);
    dst[0] = o0;
    dst[1] = o1;
}

// ---------------------------------------------------------------------------
// 5. out = agg @ W^T + b   (agg already normalized, fp32)
// ---------------------------------------------------------------------------
__global__ __launch_bounds__(256) void out_kernel(
    const float* __restrict__ W,
    const float* __restrict__ b,
    float* __restrict__ out,
    int n)
{
    __shared__ float sW[64 * 68];
    __shared__ float sA[64 * 68];
    __shared__ float sB[64];

    const int tid  = threadIdx.x;
    const int base = blockIdx.x * 64;

    for (int idx = tid; idx < 64 * 64; idx += 256) {
        int j = idx >> 6;
        int k = idx & 63;
        sW[k * 68 + j] = W[idx];
    }
    if (tid < 64) sB[tid] = b[tid];

    #pragma unroll
    for (int p = 0; p < 4; p++) {
        int idx  = tid + p * 256;
        int nd   = idx >> 4;
        int ch   = idx & 15;
        int node = base + nd;
        float4 v = make_float4(0.f, 0.f, 0.f, 0.f);
        if (node < n)
            v = *(const float4*)&g_agg[(size_t)node * DIM + ch * 4];
        *(float4*)&sA[nd * 68 + ch * 4] = v;
    }
    __syncthreads();

    const int tx = tid & 15;
    const int ty = tid >> 4;

    float acc[4][4];
    #pragma unroll
    for (int i = 0; i < 4; i++)
        #pragma unroll
        for (int c = 0; c < 4; c++)
            acc[i][c] = 0.f;

    #pragma unroll
    for (int k = 0; k < 64; k += 4) {
        float4 wv0 = *(const float4*)&sW[(k + 0) * 68 + tx * 4];
        float4 wv1 = *(const float4*)&sW[(k + 1) * 68 + tx * 4];
        float4 wv2 = *(const float4*)&sW[(k + 2) * 68 + tx * 4];
        float4 wv3 = *(const float4*)&sW[(k + 3) * 68 + tx * 4];
        #pragma unroll
        for (int i = 0; i < 4; i++) {
            float4 av = *(const float4*)&sA[(ty * 4 + i) * 68 + k];
            acc[i][0] += av.x * wv0.x + av.y * wv1.x + av.z * wv2.x + av.w * wv3.x;
            acc[i][1] += av.x * wv0.y + av.y * wv1.y + av.z * wv2.y + av.w * wv3.y;
            acc[i][2] += av.x * wv0.z + av.y * wv1.z + av.z * wv2.z + av.w * wv3.z;
            acc[i][3] += av.x * wv0.w + av.y * wv1.w + av.z * wv2.w + av.w * wv3.w;
        }
    }

    #pragma unroll
    for (int i = 0; i < 4; i++) {
        int node = base + ty * 4 + i;
        if (node < n) {
            float4 o;
            o.x = acc[i][0] + sB[tx * 4 + 0];
            o.y = acc[i][1] + sB[tx * 4 + 1];
            o.z = acc[i][2] + sB[tx * 4 + 2];
            o.w = acc[i][3] + sB[tx * 4 + 3];
            *(float4*)&out[(size_t)node * DIM + tx * 4] = o;
        }
    }
}

// ---------------------------------------------------------------------------
// kernel_launch — inputs: x [N*64 f32], edge_index [2*E i32], W [64*64 f32],
// b [64 f32]; output [N*64 f32].
// ---------------------------------------------------------------------------
extern "C" void kernel_launch(void* const* d_in, const int* in_sizes, int n_in,
                              void* d_out, int out_size) {
    const float* x  = (const float*)d_in[0];
    const int*   ei = (const int*)d_in[1];
    const float* W  = (const float*)d_in[2];
    const float* b  = (const float*)d_in[3];
    float*       out = (float*)d_out;

    int n = in_sizes[0] / DIM;       // 50000
    int E = in_sizes[1] / 2;         // 800000

    int eblocks = (E / 4 + 255) / 256 + 1;

    k_cvt<<<(n * (DIM / 8) + 255) / 256, 256>>>(x, n);
    k_hist<<<eblocks, 256>>>(ei, E);
    k_scan<<<1, 1024>>>();
    k_scatter<<<eblocks, 256>>>(ei, E);
    k_gather<<<(n + 31) / 32, 256>>>(n);
    out_kernel<<<(n + 63) / 64, 256>>>(W, b, out, n);
}